// round 13
// baseline (speedup 1.0000x reference)
#include <cuda_runtime.h>
#include <math.h>

// ElasticBand (NEB) — flat 3-pass scheme (R -> S -> O) at the DRAM roofline.
// R: one block per (interior image, atom band); KPT=8 -> 32 independent float4
//    loads per thread, one block reduce per 2048 float4, partial -> L2.
//    Image on blockIdx.x: each wave spans all images for a band, so the 3x pos
//    reads dedup in L2 (DRAM ~ pos once + frc once).
// S: per-image fold of band partials; eng logic recomputed inline.
// O: 2D grid (image, band), KPT=4: uniform image index (no div), coefficients
//    uniform per block, 16 independent loads per thread before any FMA.

#define KMAXC 0.1f
#define DLTKC 0.02f
#define EPSC  0.1f
#define PI_F  3.14159265358979323846f

#define TA    256                // threads per block (R)
#define KPT   8                  // float4 per thread (R)
#define TILEA (TA * KPT)         // 2048 float4 per block
#define TO    256                // threads per block (O)
#define KPO   4                  // float4 per thread (O)
#define TILEO (TO * KPO)         // 1024 float4 per block
#define MAX_INT 62
#define MAX_NB  1280

__device__ float g_part[(size_t)MAX_INT * MAX_NB * 6];  // [ii][band][6]
__device__ float g_coef[MAX_INT * 4];                    // g1, alpha, beta

__device__ __forceinline__ float warpSum(float v) {
    #pragma unroll
    for (int o = 16; o > 0; o >>= 1) v += __shfl_xor_sync(0xffffffffu, v, o);
    return v;
}

__device__ __forceinline__ float spring_k(float ea, float eb, float emax, float eref) {
    float ei = fmaxf(ea, eb);
    float k = KMAXC - DLTKC * (emax - ei) / (emax - eref);
    if (ei < eref) k = KMAXC - DLTKC;
    return k;
}

// ---- R: flat 2D reduce. block = (image ii = blockIdx.x, band b = blockIdx.y) --
__global__ void __launch_bounds__(TA) nebReduceF(
    const float4* __restrict__ pos4,
    const float4* __restrict__ frc4,
    int nvec, int nb)
{
    const int ii = blockIdx.x;        // interior index
    const int i  = ii + 1;            // global image
    const int b  = blockIdx.y;        // atom band
    const int t  = threadIdx.x;

    float vA = 0.f, vB = 0.f, vC = 0.f, vD = 0.f, vE = 0.f, vW = 0.f;

    const int j0 = b * TILEA + t;
    const size_t imgBase = (size_t)i * nvec;

    #pragma unroll
    for (int k = 0; k < KPT; k++) {
        const int j = j0 + k * TA;
        if (j < nvec) {
            const size_t base = imgBase + j;
            float4 pm = pos4[base - nvec];
            float4 pc = pos4[base];
            float4 pp = pos4[base + nvec];
            float4 f  = frc4[base];

            float dpx = pc.x - pm.x, dmx = pp.x - pc.x;
            float dpy = pc.y - pm.y, dmy = pp.y - pc.y;
            float dpz = pc.z - pm.z, dmz = pp.z - pc.z;
            float dpw = pc.w - pm.w, dmw = pp.w - pc.w;

            vA = fmaf(dpx, dpx, fmaf(dpy, dpy, fmaf(dpz, dpz, fmaf(dpw, dpw, vA))));
            vB = fmaf(dmx, dmx, fmaf(dmy, dmy, fmaf(dmz, dmz, fmaf(dmw, dmw, vB))));
            vC = fmaf(dpx, dmx, fmaf(dpy, dmy, fmaf(dpz, dmz, fmaf(dpw, dmw, vC))));
            vD = fmaf(f.x, dpx, fmaf(f.y, dpy, fmaf(f.z, dpz, fmaf(f.w, dpw, vD))));
            vE = fmaf(f.x, dmx, fmaf(f.y, dmy, fmaf(f.z, dmz, fmaf(f.w, dmw, vE))));
            vW = fmaf(f.x, f.x, fmaf(f.y, f.y, fmaf(f.z, f.z, fmaf(f.w, f.w, vW))));
        }
    }

    __shared__ float sred[6][TA / 32];
    float vals[6] = { vA, vB, vC, vD, vE, vW };
    #pragma unroll
    for (int c = 0; c < 6; c++) {
        float r = warpSum(vals[c]);
        if ((t & 31) == 0) sred[c][t >> 5] = r;
    }
    __syncthreads();
    if (t < 6) {
        float s = 0.f;
        #pragma unroll
        for (int w = 0; w < TA / 32; w++) s += sred[t][w];
        g_part[((size_t)ii * nb + b) * 6 + t] = s;
    }
}

// ---- S: fold band partials + inline eng logic -> coefficients -----------------
__global__ void nebScalars(const float* __restrict__ eng, int n_img, int nb)
{
    const int j = blockIdx.x;    // interior index
    const int t = threadIdx.x;   // 256

    float acc[6] = {0.f, 0.f, 0.f, 0.f, 0.f, 0.f};
    for (int b = t; b < nb; b += blockDim.x) {
        const float* pp = &g_part[((size_t)j * nb + b) * 6];
        #pragma unroll
        for (int c = 0; c < 6; c++) acc[c] += pp[c];
    }

    __shared__ float sred[6][8];
    #pragma unroll
    for (int c = 0; c < 6; c++) {
        float r = warpSum(acc[c]);
        if ((t & 31) == 0) sred[c][t >> 5] = r;
    }
    __syncthreads();

    if (t == 0) {
        float S[6];
        #pragma unroll
        for (int c = 0; c < 6; c++) {
            float s = 0.f;
            #pragma unroll
            for (int w = 0; w < 8; w++) s += sred[c][w];
            S[c] = s;
        }
        const float A = S[0], B = S[1], C = S[2], D = S[3], E = S[4], W = S[5];

        float emin = eng[0], emax = eng[0];
        int imax = 0;
        for (int p = 1; p < n_img; p++) {
            float e = eng[p];
            if (e < emin) emin = e;
            if (e > emax) { emax = e; imax = p; }   // strict > keeps first max
        }
        const float eref = emin - EPSC;

        const int i = j + 1;
        const float e0 = eng[i - 1], e1 = eng[i], e2 = eng[i + 1];
        const float km = spring_k(e0, e1, emax, eref);
        const float kp = spring_k(e1, e2, emax, eref);

        float cp, cm;
        if (e2 > e1 && e1 > e0)      { cp = 1.f;  cm = 0.f; }
        else if (e2 < e1 && e1 < e0) { cp = 0.f;  cm = 1.f; }
        else {
            float d1 = fabsf(e2 - e1), d0 = fabsf(e0 - e1);
            float dvmax = fmaxf(d1, d0), dvmin = fminf(d1, d0);
            if (e2 > e1)      { cp = dvmax; cm = dvmin; }
            else if (e2 < e1) { cp = dvmin; cm = dvmax; }
            else              { cp = 0.f;   cm = 0.f; }
        }
        const float mu = (j == imax) ? 2.f : 1.f;   // .at[i_raw] quirk

        const float Stt = cp * cp * A + 2.f * cp * cm * C + cm * cm * B;
        const float Sft = cp * D + cm * E;
        const float a   = Sft / Stt;
        const float s   = (kp * sqrtf(B) - km * sqrtf(A)) / sqrtf(Stt);

        const float F   = W - Sft * Sft / Stt;
        const float Tm  = cp * C + cm * B;
        const float Tp  = cp * A + cm * C;
        const float St  = kp * Tm - km * Tp;
        const float Gv  = kp * kp * B + km * km * A - 2.f * kp * km * C
                          - 2.f * s * St + s * s * Stt;
        const float Sf  = kp * E - km * D;
        const float H   = Sf - a * St - s * Sft + s * a * Stt;

        const float sw  = (2.0f / PI_F) * atan2f(F, Gv);
        const float Hsw = H * sw;

        g_coef[j * 4 + 0] = 1.f - Hsw;
        g_coef[j * 4 + 1] = a * (Hsw - mu) * cp - km;
        g_coef[j * 4 + 2] = a * (Hsw - mu) * cm + kp;
    }
}

// ---- O: 2D flat output. block = (image = blockIdx.x, band = blockIdx.y) -------
__global__ void __launch_bounds__(TO) nebOut2(
    const float4* __restrict__ pos4,
    const float4* __restrict__ frc4,
    float4* __restrict__ out4,
    int nvec, int n_img)
{
    const int img = blockIdx.x;
    const int b   = blockIdx.y;
    const int t   = threadIdx.x;

    const int j0 = b * TILEO + t;
    const size_t imgBase = (size_t)img * nvec;

    if (img == 0 || img == n_img - 1) {
        #pragma unroll
        for (int k = 0; k < KPO; k++) {
            const int j = j0 + k * TO;
            if (j < nvec) out4[imgBase + j] = frc4[imgBase + j];
        }
        return;
    }

    const int ii = img - 1;
    const float g1 = __ldg(&g_coef[ii * 4 + 0]);
    const float al = __ldg(&g_coef[ii * 4 + 1]);
    const float be = __ldg(&g_coef[ii * 4 + 2]);

    float4 f[KPO], pm[KPO], pc[KPO], pp[KPO];
    bool ok[KPO];
    #pragma unroll
    for (int k = 0; k < KPO; k++) {
        const int j = j0 + k * TO;
        ok[k] = (j < nvec);
        if (ok[k]) {
            const size_t base = imgBase + j;
            f[k]  = frc4[base];
            pm[k] = pos4[base - nvec];
            pc[k] = pos4[base];
            pp[k] = pos4[base + nvec];
        }
    }

    #pragma unroll
    for (int k = 0; k < KPO; k++) {
        if (ok[k]) {
            float4 o;
            o.x = fmaf(g1, f[k].x, fmaf(al, pc[k].x - pm[k].x, be * (pp[k].x - pc[k].x)));
            o.y = fmaf(g1, f[k].y, fmaf(al, pc[k].y - pm[k].y, be * (pp[k].y - pc[k].y)));
            o.z = fmaf(g1, f[k].z, fmaf(al, pc[k].z - pm[k].z, be * (pp[k].z - pc[k].z)));
            o.w = fmaf(g1, f[k].w, fmaf(al, pc[k].w - pm[k].w, be * (pp[k].w - pc[k].w)));
            out4[imgBase + j0 + k * TO] = o;
        }
    }
}

// =============================================================================
extern "C" void kernel_launch(void* const* d_in, const int* in_sizes, int n_in,
                              void* d_out, int out_size)
{
    const float* pos = (const float*)d_in[0];
    const float* frc = (const float*)d_in[1];
    const float* eng = (const float*)d_in[2];

    const int n_img    = in_sizes[2];                 // 32
    const long per_img = (long)in_sizes[0] / n_img;   // 1,200,000 floats
    const int  nvec    = (int)(per_img / 4);          // 300,000 float4
    const int  n_int   = n_img - 2;

    const float4* pos4 = (const float4*)pos;
    const float4* frc4 = (const float4*)frc;
    float4* out4 = (float4*)d_out;

    const int nb  = (nvec + TILEA - 1) / TILEA;       // 147 bands (R)
    const int nbO = (nvec + TILEO - 1) / TILEO;       // 293 bands (O)

    if (n_int < 1) {
        nebOut2<<<dim3(n_img, nbO), TO>>>(pos4, frc4, out4, nvec, n_img);
        return;
    }

    nebReduceF<<<dim3(n_int, nb), TA>>>(pos4, frc4, nvec, nb);
    nebScalars<<<n_int, 256>>>(eng, n_img, nb);
    nebOut2<<<dim3(n_img, nbO), TO>>>(pos4, frc4, out4, nvec, n_img);
}

// round 15
// speedup vs baseline: 1.0018x; 1.0018x over previous
#include <cuda_runtime.h>
#include <math.h>

// ElasticBand (NEB) — flat 3-pass scheme (R -> S -> O) at the DRAM roofline.
// R: PAIRED images per block: block = (image pair, atom band). Images (i, i+1)
//    share the pos window [i-1 .. i+2]: 4 pos loads per element for 2 images
//    (vs 6 flat), and dp(i+1) == dm(i), A(i+1) == B(i) -> 11 accumulators.
//    Cuts R's LTS traffic below the ~6300 B/cyc L2 ceiling so DRAM binds.
// S: per-image fold of band partials; eng logic recomputed inline. (R11 proven)
// O: flat 1D streaming out = g1*frc + alpha*dp + beta*dm.        (R11 proven)

#define KMAXC 0.1f
#define DLTKC 0.02f
#define EPSC  0.1f
#define PI_F  3.14159265358979323846f

#define TA    256                // threads per block (R)
#define KPT   4                  // float4 per thread (R)
#define TILEA (TA * KPT)         // 1024 float4 per block
#define MAX_INT 62
#define MAX_NB  1280

__device__ float g_part[(size_t)MAX_INT * MAX_NB * 6];  // [ii][band][6]
__device__ float g_coef[MAX_INT * 4];                    // g1, alpha, beta

__device__ __forceinline__ float warpSum(float v) {
    #pragma unroll
    for (int o = 16; o > 0; o >>= 1) v += __shfl_xor_sync(0xffffffffu, v, o);
    return v;
}

__device__ __forceinline__ float spring_k(float ea, float eb, float emax, float eref) {
    float ei = fmaxf(ea, eb);
    float k = KMAXC - DLTKC * (emax - ei) / (emax - eref);
    if (ei < eref) k = KMAXC - DLTKC;
    return k;
}

// ---- R: paired flat reduce. block = (pair px = blockIdx.x, band b = blockIdx.y)
__global__ void __launch_bounds__(TA) nebReduceP(
    const float4* __restrict__ pos4,
    const float4* __restrict__ frc4,
    int nvec, int n_int, int nb)
{
    const int px  = blockIdx.x;
    const int iiA = 2 * px;            // interior index of image A
    const int iA  = iiA + 1;           // global image A
    const bool hasB = (iiA + 1) < n_int;
    const int b   = blockIdx.y;
    const int t   = threadIdx.x;

    // sums: [0]=A_A [1]=B_A [2]=C_A [3]=D_A [4]=E_A [5]=W_A
    //       [6]=B_B [7]=C_B [8]=D_B [9]=E_B [10]=W_B   (A_B == B_A)
    float v0=0.f,v1=0.f,v2=0.f,v3=0.f,v4=0.f,v5=0.f;
    float v6=0.f,v7=0.f,v8=0.f,v9=0.f,v10=0.f;

    const int j0 = b * TILEA + t;
    const size_t imgBase = (size_t)iA * nvec;

    #pragma unroll
    for (int k = 0; k < KPT; k++) {
        const int j = j0 + k * TA;
        if (j < nvec) {
            const size_t base = imgBase + j;
            float4 p0 = pos4[base - nvec];
            float4 p1 = pos4[base];
            float4 p2 = pos4[base + nvec];
            float4 fA = frc4[base];

            float dpx = p1.x - p0.x, dmx = p2.x - p1.x;
            float dpy = p1.y - p0.y, dmy = p2.y - p1.y;
            float dpz = p1.z - p0.z, dmz = p2.z - p1.z;
            float dpw = p1.w - p0.w, dmw = p2.w - p1.w;

            v0 = fmaf(dpx, dpx, fmaf(dpy, dpy, fmaf(dpz, dpz, fmaf(dpw, dpw, v0))));
            v1 = fmaf(dmx, dmx, fmaf(dmy, dmy, fmaf(dmz, dmz, fmaf(dmw, dmw, v1))));
            v2 = fmaf(dpx, dmx, fmaf(dpy, dmy, fmaf(dpz, dmz, fmaf(dpw, dmw, v2))));
            v3 = fmaf(fA.x, dpx, fmaf(fA.y, dpy, fmaf(fA.z, dpz, fmaf(fA.w, dpw, v3))));
            v4 = fmaf(fA.x, dmx, fmaf(fA.y, dmy, fmaf(fA.z, dmz, fmaf(fA.w, dmw, v4))));
            v5 = fmaf(fA.x, fA.x, fmaf(fA.y, fA.y, fmaf(fA.z, fA.z, fmaf(fA.w, fA.w, v5))));

            if (hasB) {
                float4 p3 = pos4[base + 2 * (size_t)nvec];
                float4 fB = frc4[base + nvec];
                float ex = p3.x - p2.x, ey = p3.y - p2.y;
                float ez = p3.z - p2.z, ew = p3.w - p2.w;
                // image B: dp = dm(A), dm = e
                v6  = fmaf(ex, ex, fmaf(ey, ey, fmaf(ez, ez, fmaf(ew, ew, v6))));
                v7  = fmaf(dmx, ex, fmaf(dmy, ey, fmaf(dmz, ez, fmaf(dmw, ew, v7))));
                v8  = fmaf(fB.x, dmx, fmaf(fB.y, dmy, fmaf(fB.z, dmz, fmaf(fB.w, dmw, v8))));
                v9  = fmaf(fB.x, ex, fmaf(fB.y, ey, fmaf(fB.z, ez, fmaf(fB.w, ew, v9))));
                v10 = fmaf(fB.x, fB.x, fmaf(fB.y, fB.y, fmaf(fB.z, fB.z, fmaf(fB.w, fB.w, v10))));
            }
        }
    }

    __shared__ float sred[11][TA / 32];
    __shared__ float sfin[11];
    float vals[11] = { v0,v1,v2,v3,v4,v5,v6,v7,v8,v9,v10 };
    #pragma unroll
    for (int c = 0; c < 11; c++) {
        float r = warpSum(vals[c]);
        if ((t & 31) == 0) sred[c][t >> 5] = r;
    }
    __syncthreads();
    if (t < 11) {
        float s = 0.f;
        #pragma unroll
        for (int w = 0; w < TA / 32; w++) s += sred[t][w];
        sfin[t] = s;
    }
    __syncthreads();
    if (t < 6) {
        g_part[((size_t)iiA * nb + b) * 6 + t] = sfin[t];
    } else if (hasB && t >= 32 && t < 38) {
        // image B partials: [A_B, B_B, C_B, D_B, E_B, W_B] = sfin[{1,6,7,8,9,10}]
        const int c = t - 32;
        const int src = (c == 0) ? 1 : (5 + c);
        g_part[((size_t)(iiA + 1) * nb + b) * 6 + c] = sfin[src];
    }
}

// ---- S: fold band partials + inline eng logic -> coefficients (R11 proven) ----
__global__ void nebScalars(const float* __restrict__ eng, int n_img, int nb)
{
    const int j = blockIdx.x;    // interior index
    const int t = threadIdx.x;   // 256

    float acc[6] = {0.f, 0.f, 0.f, 0.f, 0.f, 0.f};
    for (int b = t; b < nb; b += blockDim.x) {
        const float* pp = &g_part[((size_t)j * nb + b) * 6];
        #pragma unroll
        for (int c = 0; c < 6; c++) acc[c] += pp[c];
    }

    __shared__ float sred[6][8];
    #pragma unroll
    for (int c = 0; c < 6; c++) {
        float r = warpSum(acc[c]);
        if ((t & 31) == 0) sred[c][t >> 5] = r;
    }
    __syncthreads();

    if (t == 0) {
        float S[6];
        #pragma unroll
        for (int c = 0; c < 6; c++) {
            float s = 0.f;
            #pragma unroll
            for (int w = 0; w < 8; w++) s += sred[c][w];
            S[c] = s;
        }
        const float A = S[0], B = S[1], C = S[2], D = S[3], E = S[4], W = S[5];

        float emin = eng[0], emax = eng[0];
        int imax = 0;
        for (int p = 1; p < n_img; p++) {
            float e = eng[p];
            if (e < emin) emin = e;
            if (e > emax) { emax = e; imax = p; }   // strict > keeps first max
        }
        const float eref = emin - EPSC;

        const int i = j + 1;
        const float e0 = eng[i - 1], e1 = eng[i], e2 = eng[i + 1];
        const float km = spring_k(e0, e1, emax, eref);
        const float kp = spring_k(e1, e2, emax, eref);

        float cp, cm;
        if (e2 > e1 && e1 > e0)      { cp = 1.f;  cm = 0.f; }
        else if (e2 < e1 && e1 < e0) { cp = 0.f;  cm = 1.f; }
        else {
            float d1 = fabsf(e2 - e1), d0 = fabsf(e0 - e1);
            float dvmax = fmaxf(d1, d0), dvmin = fminf(d1, d0);
            if (e2 > e1)      { cp = dvmax; cm = dvmin; }
            else if (e2 < e1) { cp = dvmin; cm = dvmax; }
            else              { cp = 0.f;   cm = 0.f; }
        }
        const float mu = (j == imax) ? 2.f : 1.f;   // .at[i_raw] quirk

        const float Stt = cp * cp * A + 2.f * cp * cm * C + cm * cm * B;
        const float Sft = cp * D + cm * E;
        const float a   = Sft / Stt;
        const float s   = (kp * sqrtf(B) - km * sqrtf(A)) / sqrtf(Stt);

        const float F   = W - Sft * Sft / Stt;
        const float Tm  = cp * C + cm * B;
        const float Tp  = cp * A + cm * C;
        const float St  = kp * Tm - km * Tp;
        const float Gv  = kp * kp * B + km * km * A - 2.f * kp * km * C
                          - 2.f * s * St + s * s * Stt;
        const float Sf  = kp * E - km * D;
        const float H   = Sf - a * St - s * Sft + s * a * Stt;

        const float sw  = (2.0f / PI_F) * atan2f(F, Gv);
        const float Hsw = H * sw;

        g_coef[j * 4 + 0] = 1.f - Hsw;
        g_coef[j * 4 + 1] = a * (Hsw - mu) * cp - km;
        g_coef[j * 4 + 2] = a * (Hsw - mu) * cm + kp;
    }
}

// ---- O: flat 1D streaming output (R11 proven) ----------------------------------
__global__ void nebOut(
    const float4* __restrict__ pos4,
    const float4* __restrict__ frc4,
    float4* __restrict__ out4,
    int nvec, int n_img)
{
    size_t gid = (size_t)blockIdx.x * blockDim.x + threadIdx.x;
    size_t total = (size_t)n_img * nvec;
    if (gid >= total) return;

    int img = (int)(gid / (unsigned)nvec);
    float4 f = frc4[gid];

    if (img == 0 || img == n_img - 1) { out4[gid] = f; return; }

    const int ii = img - 1;
    const float g1 = __ldg(&g_coef[ii * 4 + 0]);
    const float al = __ldg(&g_coef[ii * 4 + 1]);
    const float be = __ldg(&g_coef[ii * 4 + 2]);

    float4 pm = pos4[gid - nvec];
    float4 pc = pos4[gid];
    float4 pp = pos4[gid + nvec];

    float4 o;
    o.x = fmaf(g1, f.x, fmaf(al, pc.x - pm.x, be * (pp.x - pc.x)));
    o.y = fmaf(g1, f.y, fmaf(al, pc.y - pm.y, be * (pp.y - pc.y)));
    o.z = fmaf(g1, f.z, fmaf(al, pc.z - pm.z, be * (pp.z - pc.z)));
    o.w = fmaf(g1, f.w, fmaf(al, pc.w - pm.w, be * (pp.w - pc.w)));
    out4[gid] = o;
}

// =============================================================================
extern "C" void kernel_launch(void* const* d_in, const int* in_sizes, int n_in,
                              void* d_out, int out_size)
{
    const float* pos = (const float*)d_in[0];
    const float* frc = (const float*)d_in[1];
    const float* eng = (const float*)d_in[2];

    const int n_img    = in_sizes[2];                 // 32
    const long per_img = (long)in_sizes[0] / n_img;   // 1,200,000 floats
    const int  nvec    = (int)(per_img / 4);          // 300,000 float4
    const int  n_int   = n_img - 2;

    const float4* pos4 = (const float4*)pos;
    const float4* frc4 = (const float4*)frc;
    float4* out4 = (float4*)d_out;

    const int nb    = (nvec + TILEA - 1) / TILEA;     // 293 bands (R, S)
    const int npair = (n_int + 1) / 2;                // 15 image pairs

    size_t total = (size_t)n_img * nvec;
    int blocksC = (int)((total + 255) / 256);

    if (n_int < 1) {
        nebOut<<<blocksC, 256>>>(pos4, frc4, out4, nvec, n_img);
        return;
    }

    nebReduceP<<<dim3(npair, nb), TA>>>(pos4, frc4, nvec, n_int, nb);
    nebScalars<<<n_int, 256>>>(eng, n_img, nb);
    nebOut<<<blocksC, 256>>>(pos4, frc4, out4, nvec, n_img);
}

// round 16
// speedup vs baseline: 1.0205x; 1.0187x over previous
#include <cuda_runtime.h>
#include <math.h>

// ElasticBand (NEB) — flat 3-pass scheme (R -> S -> O) at the DRAM roofline.
// This is the proven-best configuration (R11, 125.1us):
// R: one block per (interior image, atom band); KPT=8 -> 32 independent float4
//    loads per thread, one block reduce per 2048 float4, partial -> L2.
//    Image on blockIdx.x: each wave spans all images for a band, so the 3x pos
//    reads dedup in L2 (DRAM ~ pos once + frc once). 49.4us @ 6.1 TB/s.
// S: per-image fold of band partials; eng logic recomputed inline (~1us).
// O: flat 1D streaming out = g1*frc + alpha*dp + beta*dm; pos reads L2-deduped.
//    ~72us @ 6.3 TB/s effective.
// Total DRAM traffic ~760MB = the 2-pass structural floor at the achieved ceiling.

#define KMAXC 0.1f
#define DLTKC 0.02f
#define EPSC  0.1f
#define PI_F  3.14159265358979323846f

#define TA    256                // threads per block (R)
#define KPT   8                  // float4 per thread (R)
#define TILEA (TA * KPT)         // 2048 float4 per block
#define MAX_INT 62
#define MAX_NB  1280

__device__ float g_part[(size_t)MAX_INT * MAX_NB * 6];  // [ii][band][6]
__device__ float g_coef[MAX_INT * 4];                    // g1, alpha, beta

__device__ __forceinline__ float warpSum(float v) {
    #pragma unroll
    for (int o = 16; o > 0; o >>= 1) v += __shfl_xor_sync(0xffffffffu, v, o);
    return v;
}

__device__ __forceinline__ float spring_k(float ea, float eb, float emax, float eref) {
    float ei = fmaxf(ea, eb);
    float k = KMAXC - DLTKC * (emax - ei) / (emax - eref);
    if (ei < eref) k = KMAXC - DLTKC;
    return k;
}

// ---- R: flat 2D reduce. block = (image ii = blockIdx.x, band b = blockIdx.y) --
__global__ void __launch_bounds__(TA) nebReduceF(
    const float4* __restrict__ pos4,
    const float4* __restrict__ frc4,
    int nvec, int nb)
{
    const int ii = blockIdx.x;        // interior index
    const int i  = ii + 1;            // global image
    const int b  = blockIdx.y;        // atom band
    const int t  = threadIdx.x;

    float vA = 0.f, vB = 0.f, vC = 0.f, vD = 0.f, vE = 0.f, vW = 0.f;

    const int j0 = b * TILEA + t;
    const size_t imgBase = (size_t)i * nvec;

    #pragma unroll
    for (int k = 0; k < KPT; k++) {
        const int j = j0 + k * TA;
        if (j < nvec) {
            const size_t base = imgBase + j;
            float4 pm = pos4[base - nvec];
            float4 pc = pos4[base];
            float4 pp = pos4[base + nvec];
            float4 f  = frc4[base];

            float dpx = pc.x - pm.x, dmx = pp.x - pc.x;
            float dpy = pc.y - pm.y, dmy = pp.y - pc.y;
            float dpz = pc.z - pm.z, dmz = pp.z - pc.z;
            float dpw = pc.w - pm.w, dmw = pp.w - pc.w;

            vA = fmaf(dpx, dpx, fmaf(dpy, dpy, fmaf(dpz, dpz, fmaf(dpw, dpw, vA))));
            vB = fmaf(dmx, dmx, fmaf(dmy, dmy, fmaf(dmz, dmz, fmaf(dmw, dmw, vB))));
            vC = fmaf(dpx, dmx, fmaf(dpy, dmy, fmaf(dpz, dmz, fmaf(dpw, dmw, vC))));
            vD = fmaf(f.x, dpx, fmaf(f.y, dpy, fmaf(f.z, dpz, fmaf(f.w, dpw, vD))));
            vE = fmaf(f.x, dmx, fmaf(f.y, dmy, fmaf(f.z, dmz, fmaf(f.w, dmw, vE))));
            vW = fmaf(f.x, f.x, fmaf(f.y, f.y, fmaf(f.z, f.z, fmaf(f.w, f.w, vW))));
        }
    }

    __shared__ float sred[6][TA / 32];
    float vals[6] = { vA, vB, vC, vD, vE, vW };
    #pragma unroll
    for (int c = 0; c < 6; c++) {
        float r = warpSum(vals[c]);
        if ((t & 31) == 0) sred[c][t >> 5] = r;
    }
    __syncthreads();
    if (t < 6) {
        float s = 0.f;
        #pragma unroll
        for (int w = 0; w < TA / 32; w++) s += sred[t][w];
        g_part[((size_t)ii * nb + b) * 6 + t] = s;
    }
}

// ---- S: fold band partials + inline eng logic -> coefficients -----------------
__global__ void nebScalars(const float* __restrict__ eng, int n_img, int nb)
{
    const int j = blockIdx.x;    // interior index
    const int t = threadIdx.x;   // 256

    float acc[6] = {0.f, 0.f, 0.f, 0.f, 0.f, 0.f};
    for (int b = t; b < nb; b += blockDim.x) {
        const float* pp = &g_part[((size_t)j * nb + b) * 6];
        #pragma unroll
        for (int c = 0; c < 6; c++) acc[c] += pp[c];
    }

    __shared__ float sred[6][8];
    #pragma unroll
    for (int c = 0; c < 6; c++) {
        float r = warpSum(acc[c]);
        if ((t & 31) == 0) sred[c][t >> 5] = r;
    }
    __syncthreads();

    if (t == 0) {
        float S[6];
        #pragma unroll
        for (int c = 0; c < 6; c++) {
            float s = 0.f;
            #pragma unroll
            for (int w = 0; w < 8; w++) s += sred[c][w];
            S[c] = s;
        }
        const float A = S[0], B = S[1], C = S[2], D = S[3], E = S[4], W = S[5];

        float emin = eng[0], emax = eng[0];
        int imax = 0;
        for (int p = 1; p < n_img; p++) {
            float e = eng[p];
            if (e < emin) emin = e;
            if (e > emax) { emax = e; imax = p; }   // strict > keeps first max
        }
        const float eref = emin - EPSC;

        const int i = j + 1;
        const float e0 = eng[i - 1], e1 = eng[i], e2 = eng[i + 1];
        const float km = spring_k(e0, e1, emax, eref);
        const float kp = spring_k(e1, e2, emax, eref);

        float cp, cm;
        if (e2 > e1 && e1 > e0)      { cp = 1.f;  cm = 0.f; }
        else if (e2 < e1 && e1 < e0) { cp = 0.f;  cm = 1.f; }
        else {
            float d1 = fabsf(e2 - e1), d0 = fabsf(e0 - e1);
            float dvmax = fmaxf(d1, d0), dvmin = fminf(d1, d0);
            if (e2 > e1)      { cp = dvmax; cm = dvmin; }
            else if (e2 < e1) { cp = dvmin; cm = dvmax; }
            else              { cp = 0.f;   cm = 0.f; }
        }
        const float mu = (j == imax) ? 2.f : 1.f;   // .at[i_raw] quirk

        const float Stt = cp * cp * A + 2.f * cp * cm * C + cm * cm * B;
        const float Sft = cp * D + cm * E;
        const float a   = Sft / Stt;
        const float s   = (kp * sqrtf(B) - km * sqrtf(A)) / sqrtf(Stt);

        const float F   = W - Sft * Sft / Stt;
        const float Tm  = cp * C + cm * B;
        const float Tp  = cp * A + cm * C;
        const float St  = kp * Tm - km * Tp;
        const float Gv  = kp * kp * B + km * km * A - 2.f * kp * km * C
                          - 2.f * s * St + s * s * Stt;
        const float Sf  = kp * E - km * D;
        const float H   = Sf - a * St - s * Sft + s * a * Stt;

        const float sw  = (2.0f / PI_F) * atan2f(F, Gv);
        const float Hsw = H * sw;

        g_coef[j * 4 + 0] = 1.f - Hsw;
        g_coef[j * 4 + 1] = a * (Hsw - mu) * cp - km;
        g_coef[j * 4 + 2] = a * (Hsw - mu) * cm + kp;
    }
}

// ---- O: flat streaming output ---------------------------------------------------
__global__ void nebOut(
    const float4* __restrict__ pos4,
    const float4* __restrict__ frc4,
    float4* __restrict__ out4,
    int nvec, int n_img)
{
    size_t gid = (size_t)blockIdx.x * blockDim.x + threadIdx.x;
    size_t total = (size_t)n_img * nvec;
    if (gid >= total) return;

    int img = (int)(gid / (unsigned)nvec);
    float4 f = frc4[gid];

    if (img == 0 || img == n_img - 1) { out4[gid] = f; return; }

    const int ii = img - 1;
    const float g1 = __ldg(&g_coef[ii * 4 + 0]);
    const float al = __ldg(&g_coef[ii * 4 + 1]);
    const float be = __ldg(&g_coef[ii * 4 + 2]);

    float4 pm = pos4[gid - nvec];
    float4 pc = pos4[gid];
    float4 pp = pos4[gid + nvec];

    float4 o;
    o.x = fmaf(g1, f.x, fmaf(al, pc.x - pm.x, be * (pp.x - pc.x)));
    o.y = fmaf(g1, f.y, fmaf(al, pc.y - pm.y, be * (pp.y - pc.y)));
    o.z = fmaf(g1, f.z, fmaf(al, pc.z - pm.z, be * (pp.z - pc.z)));
    o.w = fmaf(g1, f.w, fmaf(al, pc.w - pm.w, be * (pp.w - pc.w)));
    out4[gid] = o;
}

// =============================================================================
extern "C" void kernel_launch(void* const* d_in, const int* in_sizes, int n_in,
                              void* d_out, int out_size)
{
    const float* pos = (const float*)d_in[0];
    const float* frc = (const float*)d_in[1];
    const float* eng = (const float*)d_in[2];

    const int n_img    = in_sizes[2];                 // 32
    const long per_img = (long)in_sizes[0] / n_img;   // 1,200,000 floats
    const int  nvec    = (int)(per_img / 4);          // 300,000 float4
    const int  n_int   = n_img - 2;

    const float4* pos4 = (const float4*)pos;
    const float4* frc4 = (const float4*)frc;
    float4* out4 = (float4*)d_out;

    const int nb = (nvec + TILEA - 1) / TILEA;        // 147 bands

    size_t total = (size_t)n_img * nvec;
    int blocksC = (int)((total + 255) / 256);

    if (n_int < 1) {
        nebOut<<<blocksC, 256>>>(pos4, frc4, out4, nvec, n_img);
        return;
    }

    nebReduceF<<<dim3(n_int, nb), TA>>>(pos4, frc4, nvec, nb);
    nebScalars<<<n_int, 256>>>(eng, n_img, nb);
    nebOut<<<blocksC, 256>>>(pos4, frc4, out4, nvec, n_img);
}